// round 7
// baseline (speedup 1.0000x reference)
#include <cuda_runtime.h>

// GraphPyramidPooling — adjacency (d_in[0]) is dead code. Live math:
//   s0_i = sig(h_i·w0+b0); s1 = sig(s0*(h·w1)+b1); s2 = sig(s0*s1*(h·w2)+b2)
//   out[r] = a0[r]*h[r] + g1[r]*h[src1[r]] + g2[r]*h[src2[r]]
// exact stable top-k ranks per level via u64 keys (bits(s)<<32 | ~idx).
//
// R6: ONE persistent kernel (148 CTAs, 1/SM). R5's regression was the grid
// barrier: 296 atomicAdds on ONE address serialize at the L2 atomic ALU
// (~6us/barrier). Now: 32 sliced arrival counters (128B apart) + block-0
// master that polls slice sums and broadcasts a monotonic release word.

#define D    512
#define DV   128
#define N0   4096
#define K0   3276
#define N1   3276
#define K1   1965
#define N2   1965
#define K2   786
#define NP0  4096
#define NP1  3328
#define NP2  1984
#define NB   148
#define NTH  256
#define NWARP (NB * 8)     // 1184
#define NSLICE 32

typedef unsigned long long u64;
typedef unsigned int u32;

__device__ u64   g_k0[NP0];
__device__ u64   g_k1[NP1];
__device__ u64   g_k2[NP2];
__device__ float g_s0a[N0];
__device__ float g_d1[N0];
__device__ float g_d2[N0];
__device__ float g_a0[N0];
__device__ float g_g1[N0];
__device__ float g_g2[N0];
__device__ int   g_src1[N0];
__device__ int   g_src2[N0];
__device__ int   g_inv0[N1];
__device__ int   g_p2src[N2];
__device__ float g_p2gain[N2];
__device__ u32   g_arrive[NSLICE * 32];  // monotonic; slice s at [s*32]
__device__ u32   g_release;              // monotonic completed-phase count
__device__ u32   g_epoch;                // completed launches

__device__ __forceinline__ float warp_sum(float v) {
#pragma unroll
    for (int o = 16; o; o >>= 1) v += __shfl_xor_sync(0xffffffffu, v, o);
    return v;
}
__device__ __forceinline__ float sigmoidf(float x) {
    return 1.0f / (1.0f + expf(-x));
}
__device__ __forceinline__ u64 make_key(float s, int idx) {
    return ((u64)(u32)__float_as_int(s) << 32) | (u32)(~(u32)idx);
}
__device__ __forceinline__ float key_score(u64 k) {
    return __int_as_float((int)(k >> 32));
}
__device__ __forceinline__ u32 ld_acq(const u32* p) {
    u32 v;
    asm volatile("ld.acquire.gpu.u32 %0, [%1];" : "=r"(v) : "l"(p) : "memory");
    return v;
}

// phase = 1..4 within this launch; epoch gives the monotonic base.
__device__ __forceinline__ void grid_barrier(u32 epoch, u32 phase) {
    __syncthreads();
    if (threadIdx.x == 0) {
        __threadfence();
        atomicAdd(&g_arrive[(blockIdx.x & (NSLICE - 1)) * 32], 1u);
        const u32 rel_target = epoch * 4u + phase;
        if (blockIdx.x == 0) {
            const u32 sum_target = rel_target * NB;
            u32 s;
            do {
                s = 0;
#pragma unroll
                for (int k = 0; k < NSLICE; k++) s += ld_acq(&g_arrive[k * 32]);
            } while ((int)(s - sum_target) < 0);
            __threadfence();
            asm volatile("st.release.gpu.u32 [%0], %1;"
                         :: "l"(&g_release), "r"(rel_target) : "memory");
        } else {
            while ((int)(ld_acq(&g_release) - rel_target) < 0) {}
        }
    }
    __syncthreads();
}

// One rank stage: stage level keys in smem; each warp ranks up to 4 strided
// rows against the whole array (exact stable: strict u64 >); lane 0 chains
// the per-row scalars for the next level.
template <int LVL, int NN, int NPAD, int KK>
__device__ void rank_phase(u64* smk, const float* __restrict__ b) {
    const u64* gk = (LVL == 0) ? g_k0 : (LVL == 1) ? g_k1 : g_k2;
    const ulonglong2* gk2 = (const ulonglong2*)gk;
    for (int t = threadIdx.x; t < NPAD / 2; t += NTH) {
        ulonglong2 v;
        if (2 * t + 1 < NN) v = __ldg(gk2 + t);
        else { v.x = (2 * t < NN) ? __ldg(gk + 2 * t) : 0ULL; v.y = 0ULL; }
        ((ulonglong2*)smk)[t] = v;
    }
    __syncthreads();

    const int wid  = threadIdx.x >> 5;
    const int lane = threadIdx.x & 31;
    const int gw   = blockIdx.x * 8 + wid;

    u64 ki[4];
    int cnt[4];
#pragma unroll
    for (int t = 0; t < 4; t++) {
        int i = gw + t * NWARP;
        ki[t]  = (i < NN) ? smk[i] : ~0ULL;   // ~0: nothing counts, unused
        cnt[t] = 0;
    }
    const ulonglong2* s2 = (const ulonglong2*)smk;
#pragma unroll 4
    for (int q = lane; q < NPAD / 2; q += 32) {
        ulonglong2 v = s2[q];
#pragma unroll
        for (int t = 0; t < 4; t++)
            cnt[t] += (int)(v.x > ki[t]) + (int)(v.y > ki[t]);
    }
    int pA = cnt[0] | (cnt[1] << 16);
    int pB = cnt[2] | (cnt[3] << 16);
#pragma unroll
    for (int o = 16; o; o >>= 1) {
        pA += __shfl_xor_sync(0xffffffffu, pA, o);
        pB += __shfl_xor_sync(0xffffffffu, pB, o);
    }
    if (lane != 0) return;
    const int rk[4] = { pA & 0xFFFF, pA >> 16, pB & 0xFFFF, pB >> 16 };

#pragma unroll
    for (int t = 0; t < 4; t++) {
        const int i = gw + t * NWARP;
        if (i >= NN) continue;
        const int rank = rk[t];
        const bool sel = rank < KK;
        const u64  k   = ki[t];
        if (LVL == 0) {
            float s0 = key_score(k);
            g_a0[i] = sel ? s0 : 0.f;
            if (sel) {
                float s1 = sigmoidf(s0 * g_d1[i] + b[1]);
                g_k1[rank]   = make_key(s1, rank);
                g_inv0[rank] = i;
            }
        } else if (LVL == 1) {
            int   src  = g_inv0[i];
            float s1   = key_score(k);
            float gain = g_s0a[src] * s1;
            g_g1[i]   = sel ? gain : 0.f;
            g_src1[i] = src;
            if (sel) {
                float s2v = sigmoidf(gain * g_d2[src] + b[2]);
                g_k2[rank]     = make_key(s2v, rank);
                g_p2src[rank]  = src;
                g_p2gain[rank] = gain;
            }
        } else {
            float s2v = key_score(k);
            g_g2[i]   = sel ? g_p2gain[i] * s2v : 0.f;
            g_src2[i] = g_p2src[i];
        }
    }
}

__global__ void __launch_bounds__(NTH)
mega_kernel(const float* __restrict__ h, const float* __restrict__ W,
            const float* __restrict__ b, float* __restrict__ out) {
    __shared__ __align__(16) u64 smk[NP0];   // 32KB, reused per rank phase
    const int tid  = threadIdx.x;
    const int wid  = tid >> 5;
    const int lane = tid & 31;
    const int gw   = blockIdx.x * 8 + wid;
    const u32 epoch = ld_acq(&g_epoch);   // stable until all blocks arrive

    // ---- phase 0: three dot products per row + key0 + tail inits ----
    for (int r = gw; r < N0; r += NWARP) {
        const float4* hr = (const float4*)h + (size_t)r * DV;
        const float4* w0 = (const float4*)W;
        const float4* w1 = w0 + DV;
        const float4* w2 = w0 + 2 * DV;
        float a0 = 0.f, a1 = 0.f, a2 = 0.f;
#pragma unroll
        for (int i = 0; i < 4; i++) {
            float4 a  = __ldg(hr + lane + 32 * i);
            float4 c0 = __ldg(w0 + lane + 32 * i);
            float4 c1 = __ldg(w1 + lane + 32 * i);
            float4 c2 = __ldg(w2 + lane + 32 * i);
            a0 += a.x * c0.x + a.y * c0.y + a.z * c0.z + a.w * c0.w;
            a1 += a.x * c1.x + a.y * c1.y + a.z * c1.z + a.w * c1.w;
            a2 += a.x * c2.x + a.y * c2.y + a.z * c2.z + a.w * c2.w;
        }
        a0 = warp_sum(a0); a1 = warp_sum(a1); a2 = warp_sum(a2);
        if (lane == 0) {
            float s0 = sigmoidf(a0 + b[0]);
            g_s0a[r] = s0;
            g_k0[r]  = make_key(s0, r);
            g_d1[r]  = a1;
            g_d2[r]  = a2;
            if (r >= N1) { g_g1[r] = 0.f; g_src1[r] = r; }
            if (r >= N2) { g_g2[r] = 0.f; g_src2[r] = r; }
        }
    }
    grid_barrier(epoch, 1);

    // ---- phases 1-3: exact stable ranks, scalar chaining ----
    rank_phase<0, N0, NP0, K0>(smk, b);
    grid_barrier(epoch, 2);
    rank_phase<1, N1, NP1, K1>(smk, b);
    grid_barrier(epoch, 3);
    rank_phase<2, N2, NP2, K2>(smk, b);
    grid_barrier(epoch, 4);

    // epoch advance: all blocks have passed the last barrier already
    if (blockIdx.x == 0 && tid == 0) g_epoch = epoch + 1u;

    // ---- phase 4: out[r] = a0*h[r] + g1*h[src1] + g2*h[src2] ----
    const float4* h4 = (const float4*)h;
    for (int i = blockIdx.x * NTH + tid; i < N0 * DV; i += NB * NTH) {
        int r = i >> 7;
        int c = i & 127;
        float a0 = g_a0[r];
        float g1 = g_g1[r];
        float g2 = g_g2[r];
        int   s1 = g_src1[r];
        int   s2 = g_src2[r];
        float4 v0 = __ldg(h4 + (size_t)r  * DV + c);
        float4 v1 = __ldg(h4 + (size_t)s1 * DV + c);
        float4 v2 = __ldg(h4 + (size_t)s2 * DV + c);
        float4 o;
        o.x = a0 * v0.x + g1 * v1.x + g2 * v2.x;
        o.y = a0 * v0.y + g1 * v1.y + g2 * v2.y;
        o.z = a0 * v0.z + g1 * v1.z + g2 * v2.z;
        o.w = a0 * v0.w + g1 * v1.w + g2 * v2.w;
        ((float4*)out)[i] = o;
    }
}

extern "C" void kernel_launch(void* const* d_in, const int* in_sizes, int n_in,
                              void* d_out, int out_size) {
    // inputs: [0]=g (UNUSED), [1]=h [4096,512], [2]=W [3,512], [3]=b [3]
    const float* h = (const float*)d_in[1];
    const float* W = (const float*)d_in[2];
    const float* b = (const float*)d_in[3];
    float* out = (float*)d_out;
    mega_kernel<<<NB, NTH>>>(h, W, b, out);
}

// round 8
// speedup vs baseline: 1.5107x; 1.5107x over previous
#include <cuda_runtime.h>

// GraphPyramidPooling — adjacency (d_in[0]) is dead code. Live math:
//   s0 = sig(h·w0+b0); s1 = sig(s0*(h·w1)+b1); s2 = sig(s0*s1*(h·w2)+b2)
//   out[i]        = sel0(i) ? s0*h[i] : 0                  (orig position)
//   out[rank0(i)] += sel1(i) ? s0*s1*h[i] : 0   (covered bijectively)
//   out[rank1(i)] += sel2(i) ? s0*s1*s2*h[i] : 0
// Exact stable top-k via lex keys; selection masks via exact thresholds
// T0 (u64) / T1 (128-bit) computed by K1's last-finishing block (radix
// select), so all 3 rank levels collapse into ONE kernel. 3 launches total.

typedef unsigned long long u64;
typedef unsigned int u32;

#define D    512
#define DV   128
#define NROW 4096
#define KS0  3276
#define KS1  1965
#define KS2  786

__device__ u64   g_key0[NROW];   // s0bits<<32 | ~i
__device__ u64   g_k1hi[NROW];   // s1bits<<32 | s0bits   (lo = ~i implicit)
__device__ u64   g_k2hi[NROW];   // s2bits<<32 | s1bits   (lo = s0bits<<32|~i)
__device__ float g_A0[NROW];
__device__ float g_G1[KS0];
__device__ int   g_S1[KS0];
__device__ float g_G2[KS1];
__device__ int   g_S2[KS1];
__device__ u64   g_T0;
__device__ u64   g_T1hi;
__device__ u32   g_T1lo;
__device__ u32   g_ticket;       // monotonic across replays

__device__ __forceinline__ float warp_sum(float v) {
#pragma unroll
    for (int o = 16; o; o >>= 1) v += __shfl_xor_sync(0xffffffffu, v, o);
    return v;
}
__device__ __forceinline__ float sigmoidf(float x) {
    return 1.0f / (1.0f + expf(-x));
}
__device__ __forceinline__ void reduce4(const int c[4], int r[4]) {
    int pA = c[0] | (c[1] << 16);
    int pB = c[2] | (c[3] << 16);
#pragma unroll
    for (int o = 16; o; o >>= 1) {
        pA += __shfl_xor_sync(0xffffffffu, pA, o);
        pB += __shfl_xor_sync(0xffffffffu, pB, o);
    }
    r[0] = pA & 0xFFFF; r[1] = pA >> 16;
    r[2] = pB & 0xFFFF; r[3] = pB >> 16;
}

// Exact 'want'-th largest u64 among (optionally masked) KA[0..n). Early-exits
// when the candidate set hits 1 (fetches full key + index). If it runs all 8
// bytes, *res = full prefix and *resj = -1 (duplicates possible for k1hi).
// ctl[1] keeps the residual want for a stage-2 tie-break select.
__device__ void radix_select64(const u64* KA, const u32* maskb, int n, int want,
                               u32* hist, u32* sc, int* ctl,
                               u64* res, int* resj, int nthreads) {
    const int tid = threadIdx.x;
    u64 prefix = 0, pmask = 0;
    int done = 0;
    for (int shift = 56; shift >= 0 && !done; shift -= 8) {
        if (tid < 256) hist[tid] = 0;
        __syncthreads();
        for (int j = tid; j < n; j += nthreads) {
            if (maskb && !((maskb[j >> 5] >> (j & 31)) & 1)) continue;
            u64 v = KA[j];
            if (((v ^ prefix) & pmask) == 0)
                atomicAdd(&hist[(u32)(v >> shift) & 255], 1u);
        }
        __syncthreads();
        if (tid < 256) sc[tid] = hist[tid];
        __syncthreads();
        for (int off = 1; off < 256; off <<= 1) {   // suffix sums
            u32 v2 = 0;
            if (tid < 256 && tid + off < 256) v2 = sc[tid + off];
            __syncthreads();
            if (tid < 256) sc[tid] += v2;
            __syncthreads();
        }
        if (tid < 256) {
            int ge = (int)sc[tid];
            int gt = ge - (int)hist[tid];
            if (gt < want && want <= ge) {
                ctl[0] = tid; ctl[1] = want - gt; ctl[2] = (int)hist[tid];
            }
        }
        __syncthreads();
        prefix |= ((u64)(u32)ctl[0]) << shift;
        pmask  |= ((u64)255) << shift;
        want = ctl[1];
        int cnt = ctl[2];
        __syncthreads();
        if (cnt == 1) {
            for (int j = tid; j < n; j += nthreads) {
                if (maskb && !((maskb[j >> 5] >> (j & 31)) & 1)) continue;
                u64 v = KA[j];
                if (((v ^ prefix) & pmask) == 0) { *res = v; *resj = j; }
            }
            done = 1;
        }
    }
    if (!done && tid == 0) { *res = prefix; *resj = -1; }
    __syncthreads();
}

// Stage-2: 'want'-th largest (~j) among masked j with KA[j]==hival. Rare path.
__device__ void radix_select32_lo(const u64* KA, const u32* maskb, u64 hival,
                                  int n, int want, u32* hist, u32* sc,
                                  int* ctl, u32* res32, int nthreads) {
    const int tid = threadIdx.x;
    u32 prefix = 0, pmask = 0;
    for (int shift = 24; shift >= 0; shift -= 8) {
        if (tid < 256) hist[tid] = 0;
        __syncthreads();
        for (int j = tid; j < n; j += nthreads) {
            if (!((maskb[j >> 5] >> (j & 31)) & 1)) continue;
            if (KA[j] != hival) continue;
            u32 v = ~(u32)j;
            if (((v ^ prefix) & pmask) == 0)
                atomicAdd(&hist[(v >> shift) & 255], 1u);
        }
        __syncthreads();
        if (tid < 256) sc[tid] = hist[tid];
        __syncthreads();
        for (int off = 1; off < 256; off <<= 1) {
            u32 v2 = 0;
            if (tid < 256 && tid + off < 256) v2 = sc[tid + off];
            __syncthreads();
            if (tid < 256) sc[tid] += v2;
            __syncthreads();
        }
        if (tid < 256) {
            int ge = (int)sc[tid];
            int gt = ge - (int)hist[tid];
            if (gt < want && want <= ge) { ctl[0] = tid; ctl[1] = want - gt; }
        }
        __syncthreads();
        prefix |= ((u32)ctl[0]) << shift;
        pmask  |= 255u << shift;
        want = ctl[1];
        __syncthreads();
    }
    if (tid == 0) *res32 = prefix;   // (~j) unique -> fully determined
    __syncthreads();
}

// K1: warp-per-row dots -> scores -> keys. Last-finishing block (atomic
// ticket) computes T0 and T1 via radix select in smem.
__global__ void __launch_bounds__(512)
k_scores(const float* __restrict__ h, const float* __restrict__ W,
         const float* __restrict__ b) {
    __shared__ __align__(16) u64 KA[NROW];     // 32KB
    __shared__ u32 maskb[NROW / 32];
    __shared__ u32 hist[256], sc[256];
    __shared__ int ctl[3];
    __shared__ u64 s_res;
    __shared__ int s_resj;
    __shared__ u32 s_res32;
    __shared__ int s_last;

    const int tid  = threadIdx.x;
    const int lane = tid & 31;
    const int row  = blockIdx.x * 16 + (tid >> 5);

    {
        const float4* hr = (const float4*)h + (size_t)row * DV;
        const float4* w0 = (const float4*)W;
        const float4* w1 = w0 + DV;
        const float4* w2 = w0 + 2 * DV;
        float a0 = 0.f, a1 = 0.f, a2 = 0.f;
#pragma unroll
        for (int i = 0; i < 4; i++) {
            float4 a  = __ldg(hr + lane + 32 * i);
            float4 c0 = __ldg(w0 + lane + 32 * i);
            float4 c1 = __ldg(w1 + lane + 32 * i);
            float4 c2 = __ldg(w2 + lane + 32 * i);
            a0 += a.x * c0.x + a.y * c0.y + a.z * c0.z + a.w * c0.w;
            a1 += a.x * c1.x + a.y * c1.y + a.z * c1.z + a.w * c1.w;
            a2 += a.x * c2.x + a.y * c2.y + a.z * c2.z + a.w * c2.w;
        }
        a0 = warp_sum(a0); a1 = warp_sum(a1); a2 = warp_sum(a2);
        if (lane == 0) {
            float s0 = sigmoidf(a0 + b[0]);
            float s1 = sigmoidf(s0 * a1 + b[1]);
            float s2 = sigmoidf(s0 * s1 * a2 + b[2]);
            u32 s0b = __float_as_uint(s0);
            u32 s1b = __float_as_uint(s1);
            u32 s2b = __float_as_uint(s2);
            u32 ni  = ~(u32)row;
            g_key0[row] = ((u64)s0b << 32) | ni;
            g_k1hi[row] = ((u64)s1b << 32) | s0b;
            g_k2hi[row] = ((u64)s2b << 32) | s1b;
        }
    }
    __syncthreads();
    if (tid == 0) {
        __threadfence();
        u32 t = atomicAdd(&g_ticket, 1u);
        s_last = ((t & 255) == 255);   // grid is exactly 256 blocks
    }
    __syncthreads();
    if (!s_last) return;

    // ---- last block: select T0 over key0 ----
    for (int t = tid; t < NROW / 2; t += 512)
        ((ulonglong2*)KA)[t] = __ldg((const ulonglong2*)g_key0 + t);
    __syncthreads();
    radix_select64(KA, nullptr, NROW, KS0, hist, sc, ctl, &s_res, &s_resj, 512);
    u64 T0 = s_res;
    if (tid == 0) g_T0 = T0;

    // mask0 bits
    for (int j = tid; j < NROW; j += 512) {
        u32 bal = __ballot_sync(0xffffffffu, KA[j] >= T0);
        if (lane == 0) maskb[j >> 5] = bal;
    }
    __syncthreads();

    // ---- select T1 over (k1hi, ~j) lex, masked ----
    for (int t = tid; t < NROW / 2; t += 512)
        ((ulonglong2*)KA)[t] = __ldg((const ulonglong2*)g_k1hi + t);
    __syncthreads();
    radix_select64(KA, maskb, NROW, KS1, hist, sc, ctl, &s_res, &s_resj, 512);
    if (s_resj >= 0) {
        if (tid == 0) { g_T1hi = s_res; g_T1lo = ~(u32)s_resj; }
    } else {
        u64 T1hi = s_res;
        int want2 = ctl[1];
        __syncthreads();
        radix_select32_lo(KA, maskb, T1hi, NROW, want2, hist, sc, ctl, &s_res32, 512);
        if (tid == 0) { g_T1hi = T1hi; g_T1lo = s_res32; }
    }
}

// K2: all three exact stable rank levels + scatter, one kernel.
__global__ void __launch_bounds__(256) k_rank() {
    __shared__ __align__(16) u64 A[NROW];   // 32KB, restaged per level
    __shared__ u32 Bs[NROW];                // 16KB, s0 bits (persists)
    const int tid  = threadIdx.x;
    const int wid  = tid >> 5;
    const int lane = tid & 31;
    const int ibase = blockIdx.x * 32 + wid * 4;   // 4 rows per warp
    const u64 T0   = g_T0;
    const u64 T1hi = g_T1hi;
    const u32 T1lo = g_T1lo;
    const ulonglong2* A2 = (const ulonglong2*)A;

    // ---- level 0: key0 ----
    for (int t = tid; t < NROW / 2; t += 256) {
        ulonglong2 v = __ldg((const ulonglong2*)g_key0 + t);
        ((ulonglong2*)A)[t] = v;
        Bs[2 * t]     = (u32)(v.x >> 32);
        Bs[2 * t + 1] = (u32)(v.y >> 32);
    }
    __syncthreads();
    u64 k0i[4];
#pragma unroll
    for (int t = 0; t < 4; t++) k0i[t] = A[ibase + t];
    int c[4] = {0, 0, 0, 0};
    u64 m0a = 0, m0b = 0;
    {
        int it = 0;
        for (int q = lane; q < NROW / 2; q += 32, it++) {
            ulonglong2 v = A2[q];
#pragma unroll
            for (int t = 0; t < 4; t++)
                c[t] += (int)(v.x > k0i[t]) + (int)(v.y > k0i[t]);
            u64 bits = (u64)(v.x >= T0) | ((u64)(v.y >= T0) << 1);
            if (it < 32) m0a |= bits << (2 * it);
            else         m0b |= bits << (2 * (it - 32));
        }
    }
    int r0[4]; reduce4(c, r0);
    __syncthreads();

    // ---- level 1: k1hi (lo = ~j implicit) ----
    for (int t = tid; t < NROW / 2; t += 256)
        ((ulonglong2*)A)[t] = __ldg((const ulonglong2*)g_k1hi + t);
    __syncthreads();
    u64 k1i[4]; u32 lo1i[4];
#pragma unroll
    for (int t = 0; t < 4; t++) { k1i[t] = A[ibase + t]; lo1i[t] = ~(u32)(ibase + t); }
#pragma unroll
    for (int t = 0; t < 4; t++) c[t] = 0;
    u64 m1a = 0, m1b = 0;
    {
        int it = 0;
        for (int q = lane; q < NROW / 2; q += 32, it++) {
            ulonglong2 v = A2[q];
            int j0 = 2 * q, j1 = j0 + 1;
            u32 mb = (it < 32) ? (u32)(m0a >> (2 * it)) : (u32)(m0b >> (2 * (it - 32)));
            int ma0 = mb & 1, ma1 = (mb >> 1) & 1;
            u32 l0 = ~(u32)j0, l1 = ~(u32)j1;
#pragma unroll
            for (int t = 0; t < 4; t++) {
                c[t] += ma0 & (int)((v.x > k1i[t]) | ((v.x == k1i[t]) & (l0 > lo1i[t])));
                c[t] += ma1 & (int)((v.y > k1i[t]) | ((v.y == k1i[t]) & (l1 > lo1i[t])));
            }
            u64 bits =
                (u64)(ma0 & (int)((v.x > T1hi) | ((v.x == T1hi) & (l0 >= T1lo)))) |
                ((u64)(ma1 & (int)((v.y > T1hi) | ((v.y == T1hi) & (l1 >= T1lo)))) << 1);
            if (it < 32) m1a |= bits << (2 * it);
            else         m1b |= bits << (2 * (it - 32));
        }
    }
    int r1[4]; reduce4(c, r1);
    __syncthreads();

    // ---- level 2: k2hi (lo = s0bits<<32 | ~j from Bs) ----
    for (int t = tid; t < NROW / 2; t += 256)
        ((ulonglong2*)A)[t] = __ldg((const ulonglong2*)g_k2hi + t);
    __syncthreads();
    u64 k2i[4], lo2i[4];
#pragma unroll
    for (int t = 0; t < 4; t++) {
        int i = ibase + t;
        k2i[t]  = A[i];
        lo2i[t] = ((u64)Bs[i] << 32) | (u32)(~(u32)i);
    }
#pragma unroll
    for (int t = 0; t < 4; t++) c[t] = 0;
    {
        int it = 0;
        for (int q = lane; q < NROW / 2; q += 32, it++) {
            ulonglong2 v = A2[q];
            int j0 = 2 * q, j1 = j0 + 1;
            u32 mb = (it < 32) ? (u32)(m1a >> (2 * it)) : (u32)(m1b >> (2 * (it - 32)));
            u64 lj0 = ((u64)Bs[j0] << 32) | (u32)(~(u32)j0);
            u64 lj1 = ((u64)Bs[j1] << 32) | (u32)(~(u32)j1);
#pragma unroll
            for (int t = 0; t < 4; t++) {
                c[t] += (mb & 1)        & (int)((v.x > k2i[t]) | ((v.x == k2i[t]) & (lj0 > lo2i[t])));
                c[t] += ((mb >> 1) & 1) & (int)((v.y > k2i[t]) | ((v.y == k2i[t]) & (lj1 > lo2i[t])));
            }
        }
    }
    int r2[4]; reduce4(c, r2);

    // ---- scatter (lane t handles row ibase+t; bijective, no atomics) ----
    if (lane < 4) {
        int i = ibase + lane;
        float s0 = __uint_as_float(Bs[i]);
        float s1 = __uint_as_float((u32)(k1i[lane] >> 32));
        float s2 = __uint_as_float((u32)(k2i[lane] >> 32));
        bool sel0 = r0[lane] < KS0;
        bool sel1 = sel0 && (r1[lane] < KS1);
        bool sel2 = sel1 && (r2[lane] < KS2);
        g_A0[i] = sel0 ? s0 : 0.f;
        if (sel0) { g_S1[r0[lane]] = i; g_G1[r0[lane]] = sel1 ? s0 * s1 : 0.f; }
        if (sel1) { g_S2[r1[lane]] = i; g_G2[r1[lane]] = sel2 ? s0 * s1 * s2 : 0.f; }
    }
}

// K3: out[p] = A0[p]*h[p] + G1[p]*h[S1[p]] + G2[p]*h[S2[p]]
__global__ void __launch_bounds__(256)
k_gather(const float* __restrict__ h, float* __restrict__ out) {
    int idx = blockIdx.x * 256 + threadIdx.x;   // 0 .. NROW*DV-1
    int r  = idx >> 7;
    int cc = idx & 127;
    const float4* h4 = (const float4*)h;
    float a0 = __ldg(&g_A0[r]);
    float4 v0 = __ldg(h4 + (size_t)r * DV + cc);
    float4 o;
    o.x = a0 * v0.x; o.y = a0 * v0.y; o.z = a0 * v0.z; o.w = a0 * v0.w;
    if (r < KS0) {
        float g1 = __ldg(&g_G1[r]);
        int   s1 = __ldg(&g_S1[r]);
        float4 v1 = __ldg(h4 + (size_t)s1 * DV + cc);
        o.x += g1 * v1.x; o.y += g1 * v1.y; o.z += g1 * v1.z; o.w += g1 * v1.w;
        if (r < KS1) {
            float g2 = __ldg(&g_G2[r]);
            int   s2 = __ldg(&g_S2[r]);
            float4 v2 = __ldg(h4 + (size_t)s2 * DV + cc);
            o.x += g2 * v2.x; o.y += g2 * v2.y; o.z += g2 * v2.z; o.w += g2 * v2.w;
        }
    }
    ((float4*)out)[idx] = o;
}

extern "C" void kernel_launch(void* const* d_in, const int* in_sizes, int n_in,
                              void* d_out, int out_size) {
    // inputs: [0]=g (UNUSED), [1]=h [4096,512], [2]=W [3,512], [3]=b [3]
    const float* h = (const float*)d_in[1];
    const float* W = (const float*)d_in[2];
    const float* b = (const float*)d_in[3];
    float* out = (float*)d_out;

    k_scores<<<256, 512>>>(h, W, b);
    k_rank<<<128, 256>>>();
    k_gather<<<(NROW * DV) / 256, 256>>>(h, out);
}

// round 10
// speedup vs baseline: 3.5357x; 2.3404x over previous
#include <cuda_runtime.h>

// GraphPyramidPooling — adjacency (d_in[0]) is dead code. Live math:
//   s0 = sig(h·w0+b0); s1 = sig(s0*(h·w1)+b1); s2 = sig(s0*s1*(h·w2)+b2)
//   out[r] = a0[r]*h[r] + g1[r]*h[src1[r]] + g2[r]*h[src2[r]]
// exact stable top-k per level via u64 keys (bits(s)<<32 | ~idx).
//
// R9: back to the VERIFIED R4 5-launch pipeline (no persistence, no grid
// barriers, no single-block tails). Only change: grid shapes. Rank kernels
// run at exactly 1 wave (148 blocks x 512 thr, 4 warps/SMSP) so their cost
// is one short latency chain instead of 2.5 serialized waves; the gather
// runs at full-chip thread parallelism.

#define D   512
#define DV  (D/4)
#define N0  4096
#define K0  3276
#define N1  3276
#define K1  1965
#define N2  1965
#define K2  786
#define NP0 4096
#define NP1 3328   // 3276 padded to 64
#define NP2 1984   // 1965 padded to 64

#define RNB   148          // rank kernels: 1 wave
#define RNT   512
#define RNW   (RNB * 16)   // 2368 warps

typedef unsigned long long u64;
typedef unsigned int u32;

__device__ u64   g_k0[NP0];
__device__ u64   g_k1[NP1];
__device__ u64   g_k2[NP2];
__device__ float g_s0a[N0];
__device__ float g_d1[N0];
__device__ float g_d2[N0];
__device__ float g_a0[N0];
__device__ float g_g1[N0];
__device__ float g_g2[N0];
__device__ int   g_src1[N0];
__device__ int   g_src2[N0];
__device__ int   g_inv0[N1];
__device__ int   g_p2src[N2];
__device__ float g_p2gain[N2];

__device__ __forceinline__ float warp_sum(float v) {
#pragma unroll
    for (int o = 16; o; o >>= 1) v += __shfl_xor_sync(0xffffffffu, v, o);
    return v;
}
__device__ __forceinline__ float sigmoidf(float x) {
    return 1.0f / (1.0f + expf(-x));
}
__device__ __forceinline__ u64 make_key(float s, int idx) {
    return ((u64)(u32)__float_as_int(s) << 32) | (u32)(~(u32)idx);
}
__device__ __forceinline__ float key_score(u64 k) {
    return __int_as_float((int)(k >> 32));
}

// A: one warp per row; 3 simultaneous dot products. Writes s0/key0/d1/d2 and
// zero-inits the tails of the per-level gain/src arrays.
__global__ void pass_a(const float* __restrict__ h,
                       const float* __restrict__ W,
                       const float* __restrict__ b) {
    int w    = (blockIdx.x * blockDim.x + threadIdx.x) >> 5;
    int lane = threadIdx.x & 31;
    if (w >= N0) return;
    const float4* hr = (const float4*)h + (size_t)w * DV;
    const float4* w0 = (const float4*)W;
    const float4* w1 = w0 + DV;
    const float4* w2 = w0 + 2 * DV;
    float a0 = 0.f, a1 = 0.f, a2 = 0.f;
#pragma unroll
    for (int i = 0; i < 4; i++) {
        float4 a  = __ldg(hr + lane + 32 * i);
        float4 c0 = __ldg(w0 + lane + 32 * i);
        float4 c1 = __ldg(w1 + lane + 32 * i);
        float4 c2 = __ldg(w2 + lane + 32 * i);
        a0 += a.x * c0.x + a.y * c0.y + a.z * c0.z + a.w * c0.w;
        a1 += a.x * c1.x + a.y * c1.y + a.z * c1.z + a.w * c1.w;
        a2 += a.x * c2.x + a.y * c2.y + a.z * c2.z + a.w * c2.w;
    }
    a0 = warp_sum(a0); a1 = warp_sum(a1); a2 = warp_sum(a2);
    if (lane == 0) {
        float s0 = sigmoidf(a0 + b[0]);
        g_s0a[w] = s0;
        g_k0[w]  = make_key(s0, w);
        g_d1[w]  = a1;
        g_d2[w]  = a2;
        if (w >= N1) { g_g1[w] = 0.f; g_src1[w] = w; }
        if (w >= N2) { g_g2[w] = 0.f; g_src2[w] = w; }
    }
}

// Rank kernel (1 wave): stages all level keys in smem; each warp owns WI
// rows strided by RNW; exact stable rank = #{j : key_j > key_i}; lane 0
// chains the per-row scalars for the next level.
template <int LVL, int NN, int NPAD, int KK, int WI>
__global__ void __launch_bounds__(RNT) rank_kernel(const float* __restrict__ b) {
    __shared__ __align__(16) u64 smk[NPAD];
    const u64* gk = (LVL == 0) ? g_k0 : (LVL == 1) ? g_k1 : g_k2;
    const ulonglong2* gk2 = (const ulonglong2*)gk;

    for (int t = threadIdx.x; t < NPAD / 2; t += RNT) {
        ulonglong2 v;
        if (2 * t + 1 < NN) v = __ldg(gk2 + t);
        else { v.x = (2 * t < NN) ? __ldg(gk + 2 * t) : 0ULL; v.y = 0ULL; }
        ((ulonglong2*)smk)[t] = v;
    }
    __syncthreads();

    const int wid  = threadIdx.x >> 5;
    const int lane = threadIdx.x & 31;
    const int gw   = blockIdx.x * 16 + wid;

    u64 ki[WI];
    int cnt[WI];
#pragma unroll
    for (int t = 0; t < WI; t++) {
        int i = gw + t * RNW;
        ki[t]  = (i < NN) ? smk[i] : ~0ULL;   // max key: cnt unused
        cnt[t] = 0;
    }
    const ulonglong2* s2 = (const ulonglong2*)smk;
#pragma unroll 4
    for (int q = lane; q < NPAD / 2; q += 32) {
        ulonglong2 v = s2[q];
#pragma unroll
        for (int t = 0; t < WI; t++)
            cnt[t] += (int)(v.x > ki[t]) + (int)(v.y > ki[t]);
    }
    int packed = cnt[0];
    if (WI > 1) packed |= cnt[WI - 1] << 16;
#pragma unroll
    for (int o = 16; o; o >>= 1) packed += __shfl_xor_sync(0xffffffffu, packed, o);
    if (lane != 0) return;

#pragma unroll
    for (int t = 0; t < WI; t++) {
        const int i = gw + t * RNW;
        if (i >= NN) continue;
        const int rank = (t == 0) ? (packed & 0xFFFF) : (packed >> 16);
        const bool sel = rank < KK;
        const u64  k   = ki[t];
        if (LVL == 0) {
            float s0 = key_score(k);
            g_a0[i] = sel ? s0 : 0.f;
            if (sel) {
                float s1 = sigmoidf(s0 * g_d1[i] + b[1]);
                g_k1[rank]   = make_key(s1, rank);
                g_inv0[rank] = i;
            }
        } else if (LVL == 1) {
            int   src  = g_inv0[i];
            float s1   = key_score(k);
            float gain = g_s0a[src] * s1;
            g_g1[i]   = sel ? gain : 0.f;
            g_src1[i] = src;
            if (sel) {
                float s2v = sigmoidf(gain * g_d2[src] + b[2]);
                g_k2[rank]     = make_key(s2v, rank);
                g_p2src[rank]  = src;
                g_p2gain[rank] = gain;
            }
        } else {
            float s2v = key_score(k);
            g_g2[i]   = sel ? g_p2gain[i] * s2v : 0.f;
            g_src2[i] = g_p2src[i];
        }
    }
}

// F: 1 thread per output float4. out[r] = a0*h[r] + g1*h[src1] + g2*h[src2].
__global__ void __launch_bounds__(512)
final_kernel(const float* __restrict__ h, float* __restrict__ out) {
    int tid = blockIdx.x * 512 + threadIdx.x;   // 0 .. N0*DV-1
    int r = tid >> 7;
    int c = tid & 127;
    float a0 = __ldg(g_a0 + r);
    float g1 = __ldg(g_g1 + r);
    float g2 = __ldg(g_g2 + r);
    int   s1 = __ldg(g_src1 + r);
    int   s2 = __ldg(g_src2 + r);
    const float4* h4 = (const float4*)h;
    float4 v0 = __ldg(h4 + (size_t)r  * DV + c);
    float4 v1 = __ldg(h4 + (size_t)s1 * DV + c);
    float4 v2 = __ldg(h4 + (size_t)s2 * DV + c);
    float4 o;
    o.x = a0 * v0.x + g1 * v1.x + g2 * v2.x;
    o.y = a0 * v0.y + g1 * v1.y + g2 * v2.y;
    o.z = a0 * v0.z + g1 * v1.z + g2 * v2.z;
    o.w = a0 * v0.w + g1 * v1.w + g2 * v2.w;
    ((float4*)out)[tid] = o;
}

extern "C" void kernel_launch(void* const* d_in, const int* in_sizes, int n_in,
                              void* d_out, int out_size) {
    // inputs: [0]=g (UNUSED), [1]=h [4096,512], [2]=W [3,512], [3]=b [3]
    const float* h = (const float*)d_in[1];
    const float* W = (const float*)d_in[2];
    const float* b = (const float*)d_in[3];
    float* out = (float*)d_out;

    pass_a<<<N0 / 8, 256>>>(h, W, b);
    rank_kernel<0, N0, NP0, K0, 2><<<RNB, RNT>>>(b);   // 1 wave
    rank_kernel<1, N1, NP1, K1, 2><<<RNB, RNT>>>(b);   // 1 wave
    rank_kernel<2, N2, NP2, K2, 1><<<RNB, RNT>>>(b);   // 1 wave
    final_kernel<<<(N0 * DV) / 512, 512>>>(h, out);
}